// round 7
// baseline (speedup 1.0000x reference)
#include <cuda_runtime.h>
#include <cuda_fp16.h>
#include <math.h>
#include <stdint.h>

// Problem constants
#define BSZ    256
#define HDIM   768
#define H3     2304
#define TSTEPS 128

// Tiling
#define JT       16               // j-columns per CTA (per gate)
#define NB       48               // 3 gates * JT rows of W per CTA
#define MTILE    128              // batch rows per CTA
#define KCHUNK   64               // K elems per A chunk
#define NCHUNKS  (HDIM / KCHUNK)  // 12
#define NTHREADS 512              // 16 warps
#define NJB      (HDIM / JT)      // 48
#define NCTA     96               // 48 x 2, all resident (1 CTA/SM)

// Dynamic SMEM layout (bytes)
//   W resident (single fp16): [chunk(12)][row(48)][128B], SW128 = 73728
//   A chunks: [buf(2)][part hi/lo][row(128)][128B]
#define WBYTES   (NCHUNKS * NB * 128)          // 73728
#define AOFF     WBYTES
#define APART    (MTILE * 128)                 // 16384
#define ABUF     (2 * APART)                   // 32768
#define SMEM_DYN (AOFF + 2 * ABUF)             // 139264
#define CSTRIDE  49                            // fp32 C row stride in epilogue

// ---------------------------------------------------------------------------
// Device globals
// ---------------------------------------------------------------------------
__device__ __align__(16) __half g_hhi[2][BSZ * HDIM];
__device__ __align__(16) __half g_hlo[2][BSZ * HDIM];
__device__ __align__(16) __half g_wh[H3 * HDIM];
__device__ float    g_dotp[TSTEPS * NJB * BSZ];
__device__ unsigned g_bar;

// ---------------------------------------------------------------------------
// PTX helpers (baseline sm_80/90 features only — NO tcgen05)
// ---------------------------------------------------------------------------
__device__ __forceinline__ uint32_t smem_u32(const void* p) {
    uint32_t a;
    asm("{ .reg .u64 t; cvta.to.shared.u64 t, %1; cvt.u32.u64 %0, t; }"
        : "=r"(a) : "l"(p));
    return a;
}
__device__ __forceinline__ void cp16(uint32_t d, const void* s) {
    asm volatile("cp.async.cg.shared.global [%0], [%1], 16;" :: "r"(d), "l"(s));
}
__device__ __forceinline__ void cp_commit() {
    asm volatile("cp.async.commit_group;" ::: "memory");
}
template <int N>
__device__ __forceinline__ void cp_wait() {
    asm volatile("cp.async.wait_group %0;" :: "n"(N) : "memory");
}
__device__ __forceinline__ void ldsm_x4(uint32_t* r, uint32_t a) {
    asm volatile("ldmatrix.sync.aligned.m8n8.x4.shared.b16 {%0,%1,%2,%3}, [%4];"
                 : "=r"(r[0]), "=r"(r[1]), "=r"(r[2]), "=r"(r[3]) : "r"(a));
}
__device__ __forceinline__ void ldsm_x2(uint32_t* r, uint32_t a) {
    asm volatile("ldmatrix.sync.aligned.m8n8.x2.shared.b16 {%0,%1}, [%2];"
                 : "=r"(r[0]), "=r"(r[1]) : "r"(a));
}
__device__ __forceinline__ void mma_f16(float* c, const uint32_t* a, const uint32_t* b) {
    asm volatile(
        "mma.sync.aligned.m16n8k16.row.col.f32.f16.f16.f32 "
        "{%0,%1,%2,%3}, {%4,%5,%6,%7}, {%8,%9}, {%0,%1,%2,%3};"
        : "+f"(c[0]), "+f"(c[1]), "+f"(c[2]), "+f"(c[3])
        : "r"(a[0]), "r"(a[1]), "r"(a[2]), "r"(a[3]), "r"(b[0]), "r"(b[1]));
}
#define SW128(o) ((o) ^ (((o) >> 3) & 0x70))

// ---------------------------------------------------------------------------
// Prep kernels
// ---------------------------------------------------------------------------
__global__ void prep_w_kernel(const float* __restrict__ W) {
    int i = blockIdx.x * blockDim.x + threadIdx.x;
    if (i < H3 * HDIM) g_wh[i] = __float2half_rn(W[i]);
}
__global__ void prep_h_kernel(const float* __restrict__ ctx) {
    int i = blockIdx.x * blockDim.x + threadIdx.x;
    if (i == 0) g_bar = 0u;
    if (i < BSZ * HDIM) {
        float v = ctx[i];
        __half hi = __float2half_rn(v);
        g_hhi[0][i] = hi;
        g_hlo[0][i] = __float2half_rn(v - __half2float(hi));
    }
}

// ---------------------------------------------------------------------------
// Grid barrier (96 CTAs, 1/SM, all co-resident)
// ---------------------------------------------------------------------------
__device__ __forceinline__ void grid_barrier(unsigned target) {
    __syncthreads();
    if (threadIdx.x == 0) {
        __threadfence();
        atomicAdd(&g_bar, 1u);
        unsigned v;
        do { v = *(volatile unsigned*)&g_bar; } while (v < target);
        __threadfence();
    }
    __syncthreads();
}

// ---------------------------------------------------------------------------
// Persistent kernel: all 128 GRU steps.
// Grid (48, 2), 512 threads = 16 warps, warp tile 16x24.
// 2-term fp16: C = Ah*W + Al*W  (A = h split hi/lo, W rounded once)
// Structure identical to Round-5 (2-stage, cp_wait<1>, 2 syncs/chunk).
// ---------------------------------------------------------------------------
__global__ __launch_bounds__(NTHREADS, 1) void persist_kernel(
    const float* __restrict__ context,
    const float* __restrict__ bias_ih,
    const float* __restrict__ bias_hh,
    const float* __restrict__ fc_w)
{
    extern __shared__ __align__(16) uint8_t smem[];
    __shared__ float sbr[JT], sbz[JT], sbni[JT], sbnh[JT], sfw[JT];

    const uint32_t sbase = smem_u32(smem);
    const int tid    = threadIdx.x;
    const int lane   = tid & 31;
    const int wid    = tid >> 5;
    const int warp_m = (wid & 7) * 16;     // 8 m-tiles of 16
    const int warp_n = (wid >> 3) * 24;    // 2 n-tiles of 24
    const int jb     = blockIdx.x;
    const int j0     = jb * JT;
    const int brow   = blockIdx.y * MTILE;

    // Epilogue ownership: thread = (batch row, j-quad)
    const int eb  = tid >> 2;              // 0..127
    const int ejq = (tid & 3) * 4;         // 0,4,8,12

    // ---- stage resident W (single fp16) into SMEM, SW128 swizzled ----
    for (int idx = tid; idx < NCHUNKS * NB * 8; idx += NTHREADS) {
        int ck  = idx / (NB * 8);
        int rem = idx - ck * (NB * 8);
        int r   = rem >> 3, cg = rem & 7;
        int wrow = (r >> 4) * HDIM + j0 + (r & 15);
        size_t so = (size_t)wrow * HDIM + ck * KCHUNK + cg * 8;
        uint32_t dst = (uint32_t)(ck * (NB * 128)) + SW128((uint32_t)(r * 128 + cg * 16));
        cp16(sbase + dst, g_wh + so);
    }
    cp_commit();   // W group

    if (tid < JT) {
        int j = j0 + tid;
        sbr[tid]  = bias_ih[j] + bias_hh[j];
        sbz[tid]  = bias_ih[HDIM + j] + bias_hh[HDIM + j];
        sbni[tid] = bias_ih[2 * HDIM + j];
        sbnh[tid] = bias_hh[2 * HDIM + j];
        sfw[tid]  = fc_w[j];
    }

    // fp32 h in registers: thread owns (brow+eb, j0+ejq..+3)
    float hreg[4];
    {
        const float* crow = context + (size_t)(brow + eb) * HDIM + j0 + ejq;
#pragma unroll
        for (int jj = 0; jj < 4; jj++) hreg[jj] = crow[jj];
    }
    __syncthreads();

    unsigned bar_target = 0;
    for (int t = 0; t < TSTEPS; t++) {
        const int rp = t & 1;
        const int wp = rp ^ 1;
        const __half* __restrict__ hhi = g_hhi[rp];
        const __half* __restrict__ hlo = g_hlo[rp];

        float acc[3][4];
#pragma unroll
        for (int ni = 0; ni < 3; ni++)
#pragma unroll
            for (int q = 0; q < 4; q++) acc[ni][q] = 0.0f;

        auto issueA = [&](int ck) {
            const int k0 = ck * KCHUNK;
            const uint32_t abase = sbase + AOFF + (uint32_t)(ck & 1) * ABUF;
#pragma unroll
            for (int idx = tid; idx < MTILE * 8; idx += NTHREADS) {  // 2 iters
                int r = idx >> 3, cg = idx & 7;
                uint32_t off = SW128((uint32_t)(r * 128 + cg * 16));
                size_t so = (size_t)(brow + r) * HDIM + k0 + cg * 8;
                cp16(abase + off,         hhi + so);
                cp16(abase + APART + off, hlo + so);
            }
            cp_commit();
        };

        auto compute = [&](int ck) {
            const uint32_t abase = sbase + AOFF + (uint32_t)(ck & 1) * ABUF;
            const uint32_t wbase = sbase + (uint32_t)(ck * (NB * 128));
#pragma unroll
            for (int ks = 0; ks < KCHUNK / 16; ks++) {
                const uint32_t kb = ks * 32;
                uint32_t ah[4], al[4], bw[3][2];
                {
                    uint32_t off = SW128(
                        (uint32_t)((warp_m + (lane & 15)) * 128) + kb +
                        ((lane >> 4) & 1) * 16);
                    ldsm_x4(ah, abase + off);
                    ldsm_x4(al, abase + APART + off);
                }
#pragma unroll
                for (int ni = 0; ni < 3; ni++) {
                    uint32_t off = SW128(
                        (uint32_t)((warp_n + ni * 8 + (lane & 7)) * 128) + kb +
                        ((lane >> 3) & 1) * 16);
                    ldsm_x2(bw[ni], wbase + off);
                }
#pragma unroll
                for (int ni = 0; ni < 3; ni++) {
                    mma_f16(acc[ni], ah, bw[ni]);
                    mma_f16(acc[ni], al, bw[ni]);
                }
            }
        };

        // ---- R5-style pipelined K loop: 2 stages, cp_wait<1> ----
        issueA(0);
        for (int ck = 0; ck < NCHUNKS; ck++) {
            if (ck + 1 < NCHUNKS) { issueA(ck + 1); cp_wait<1>(); }
            else                  { cp_wait<0>(); }
            __syncthreads();
            compute(ck);
            __syncthreads();
        }

        // ---- C to SMEM (aliases A buffers) ----
        float* Csm = (float*)(smem + AOFF);
        {
            const int r0 = lane >> 2, cpn = (lane & 3) * 2;
#pragma unroll
            for (int ni = 0; ni < 3; ni++) {
                int row = warp_m + r0;
                int col = warp_n + ni * 8 + cpn;
                Csm[row * CSTRIDE + col]           = acc[ni][0];
                Csm[row * CSTRIDE + col + 1]       = acc[ni][1];
                Csm[(row + 8) * CSTRIDE + col]     = acc[ni][2];
                Csm[(row + 8) * CSTRIDE + col + 1] = acc[ni][3];
            }
        }
        __syncthreads();

        // ---- gate epilogue: thread = (batch row, j-quad) ----
        {
            const int b = brow + eb;
            __half* __restrict__ hih = g_hhi[wp] + (size_t)b * HDIM + j0 + ejq;
            __half* __restrict__ hil = g_hlo[wp] + (size_t)b * HDIM + j0 + ejq;
            const float* crow = Csm + eb * CSTRIDE;

            float part = 0.0f;
#pragma unroll
            for (int q = 0; q < 4; q++) {
                const int jj = ejq + q;
                float rawr = crow[jj];
                float rawz = crow[JT + jj];
                float rawn = crow[2 * JT + jj];

                float rg = 1.0f / (1.0f + expf(-(sbr[jj] + rawr)));
                float zg = 1.0f / (1.0f + expf(-(sbz[jj] + rawz)));
                float ng = tanhf(sbni[jj] + rg * (rawn + sbnh[jj]));
                float hn = (1.0f - zg) * ng + zg * hreg[q];

                hreg[q] = hn;
                __half hi = __float2half_rn(hn);
                hih[q] = hi;
                hil[q] = __float2half_rn(hn - __half2float(hi));
                part += hn * sfw[jj];
            }
            part += __shfl_xor_sync(0xFFFFFFFFu, part, 1);
            part += __shfl_xor_sync(0xFFFFFFFFu, part, 2);
            if ((tid & 3) == 0)
                g_dotp[(size_t)t * NJB * BSZ + jb * BSZ + b] = part;
        }
        __syncthreads();   // protect Csm/A-buffer reuse by next step's issueA(0)

        bar_target += NCTA;
        if (t + 1 < TSTEPS) grid_barrier(bar_target);
    }
}

// ---------------------------------------------------------------------------
// Finalize: dot = fixed-order sum of 48 partials, softplus, scan, normalize
// ---------------------------------------------------------------------------
__device__ __forceinline__ float softplusf_(float x) {
    return (x > 0.0f) ? (x + log1pf(expf(-x))) : log1pf(expf(x));
}

__global__ __launch_bounds__(TSTEPS) void finalize_kernel(
    const int* __restrict__ num_pred,
    const float* __restrict__ fc_b,
    float* __restrict__ out)
{
    __shared__ float s[TSTEPS];
    const int b = blockIdx.x;
    const int t = threadIdx.x;

    float dot = fc_b[0];
    const float* p = g_dotp + (size_t)t * NJB * BSZ + b;
#pragma unroll
    for (int jbk = 0; jbk < NJB; jbk++) dot += p[jbk * BSZ];
    s[t] = softplusf_(dot);
    __syncthreads();

#pragma unroll
    for (int off = 1; off < TSTEPS; off <<= 1) {
        float v = (t >= off) ? s[t - off] : 0.0f;
        __syncthreads();
        s[t] += v;
        __syncthreads();
    }

    const int n = num_pred[b];
    int idx = n - 1;
    if (idx < 0) idx = 0;
    if (idx > TSTEPS - 1) idx = TSTEPS - 1;
    const float last = s[idx] + 1e-6f;

    float* orow = out + (size_t)b * (TSTEPS + 2);
    float val;
    if (t < n)       val = s[t] / last;
    else if (t == n) val = 1.0f;
    else             val = 0.0f;
    orow[t + 1] = val;

    if (t == 0) {
        orow[0] = 0.0f;
        orow[TSTEPS + 1] = (n == TSTEPS) ? 1.0f : 0.0f;
    }
}

// ---------------------------------------------------------------------------
// Launch. Inputs: 0 context 1 weight_ih(unused) 2 weight_hh 3 bias_ih
//                 4 bias_hh 5 fc_w 6 fc_b 7 num_pred_list 8 max_steps
// ---------------------------------------------------------------------------
extern "C" void kernel_launch(void* const* d_in, const int* in_sizes, int n_in,
                              void* d_out, int out_size)
{
    const float* context  = (const float*)d_in[0];
    const float* Whh      = (const float*)d_in[2];
    const float* bias_ih  = (const float*)d_in[3];
    const float* bias_hh  = (const float*)d_in[4];
    const float* fc_w     = (const float*)d_in[5];
    const float* fc_b     = (const float*)d_in[6];
    const int*   num_pred = (const int*)d_in[7];
    float*       out      = (float*)d_out;

    static bool attr_set = false;
    if (!attr_set) {
        cudaFuncSetAttribute(persist_kernel,
                             cudaFuncAttributeMaxDynamicSharedMemorySize, SMEM_DYN);
        attr_set = true;
    }

    prep_w_kernel<<<(H3 * HDIM + 255) / 256, 256>>>(Whh);
    prep_h_kernel<<<(BSZ * HDIM + 255) / 256, 256>>>(context);

    dim3 grid(NJB, BSZ / MTILE);  // (48, 2) = 96 CTAs, 1 per SM
    persist_kernel<<<grid, NTHREADS, SMEM_DYN>>>(context, bias_ih, bias_hh, fc_w);

    finalize_kernel<<<BSZ, TSTEPS>>>(num_pred, fc_b, out);
}

// round 8
// speedup vs baseline: 1.5551x; 1.5551x over previous
#include <cuda_runtime.h>
#include <cuda_bf16.h>
#include <math.h>
#include <stdint.h>

// Problem constants
#define BSZ    256
#define HDIM   768
#define H3     2304
#define TSTEPS 128

// Tiling
#define JT       16               // j-columns per CTA (per gate)
#define NB       48               // 3 gates * JT rows of W per CTA
#define MTILE    128              // batch rows per CTA
#define KCHUNK   64               // K elems per A chunk
#define NCHUNKS  (HDIM / KCHUNK)  // 12
#define NTHREADS 512              // 16 warps
#define NJB      (HDIM / JT)      // 48
#define NCTA     96               // 48 x 2, all resident (1 CTA/SM)

// Dynamic SMEM layout (bytes)
//   W resident (single bf16): [chunk(12)][row(48)][128B], SW128 = 73728
//   A chunks: [buf(2)][part hi/lo][row(128)][128B]
#define WBYTES   (NCHUNKS * NB * 128)          // 73728
#define AOFF     WBYTES
#define APART    (MTILE * 128)                 // 16384
#define ABUF     (2 * APART)                   // 32768
#define SMEM_DYN (AOFF + 2 * ABUF)             // 139264
#define CSTRIDE  49                            // fp32 C row stride in epilogue

// ---------------------------------------------------------------------------
// Device globals
// ---------------------------------------------------------------------------
__device__ __align__(16) __nv_bfloat16 g_hhi[2][BSZ * HDIM];
__device__ __align__(16) __nv_bfloat16 g_hlo[2][BSZ * HDIM];
__device__ __align__(16) __nv_bfloat16 g_wh[H3 * HDIM];    // single bf16 W
__device__ float    g_dotp[TSTEPS * NJB * BSZ];
__device__ unsigned g_bar;

// ---------------------------------------------------------------------------
// PTX helpers (baseline sm_80/90 features only — NO tcgen05)
// ---------------------------------------------------------------------------
__device__ __forceinline__ uint32_t smem_u32(const void* p) {
    uint32_t a;
    asm("{ .reg .u64 t; cvta.to.shared.u64 t, %1; cvt.u32.u64 %0, t; }"
        : "=r"(a) : "l"(p));
    return a;
}
__device__ __forceinline__ void cp16(uint32_t d, const void* s) {
    asm volatile("cp.async.cg.shared.global [%0], [%1], 16;" :: "r"(d), "l"(s));
}
__device__ __forceinline__ void cp_commit() {
    asm volatile("cp.async.commit_group;" ::: "memory");
}
template <int N>
__device__ __forceinline__ void cp_wait() {
    asm volatile("cp.async.wait_group %0;" :: "n"(N) : "memory");
}
__device__ __forceinline__ void ldsm_x4(uint32_t* r, uint32_t a) {
    asm volatile("ldmatrix.sync.aligned.m8n8.x4.shared.b16 {%0,%1,%2,%3}, [%4];"
                 : "=r"(r[0]), "=r"(r[1]), "=r"(r[2]), "=r"(r[3]) : "r"(a));
}
__device__ __forceinline__ void ldsm_x2(uint32_t* r, uint32_t a) {
    asm volatile("ldmatrix.sync.aligned.m8n8.x2.shared.b16 {%0,%1}, [%2];"
                 : "=r"(r[0]), "=r"(r[1]) : "r"(a));
}
__device__ __forceinline__ void mma_bf16(float* c, const uint32_t* a, const uint32_t* b) {
    asm volatile(
        "mma.sync.aligned.m16n8k16.row.col.f32.bf16.bf16.f32 "
        "{%0,%1,%2,%3}, {%4,%5,%6,%7}, {%8,%9}, {%0,%1,%2,%3};"
        : "+f"(c[0]), "+f"(c[1]), "+f"(c[2]), "+f"(c[3])
        : "r"(a[0]), "r"(a[1]), "r"(a[2]), "r"(a[3]), "r"(b[0]), "r"(b[1]));
}
#define SW128(o) ((o) ^ (((o) >> 3) & 0x70))

// ---------------------------------------------------------------------------
// Prep kernels
// ---------------------------------------------------------------------------
__global__ void prep_w_kernel(const float* __restrict__ W) {
    int i = blockIdx.x * blockDim.x + threadIdx.x;
    if (i < H3 * HDIM) g_wh[i] = __float2bfloat16_rn(W[i]);
}
__global__ void prep_h_kernel(const float* __restrict__ ctx) {
    int i = blockIdx.x * blockDim.x + threadIdx.x;
    if (i == 0) g_bar = 0u;
    if (i < BSZ * HDIM) {
        float v = ctx[i];
        __nv_bfloat16 hi = __float2bfloat16_rn(v);
        g_hhi[0][i] = hi;
        g_hlo[0][i] = __float2bfloat16_rn(v - __bfloat162float(hi));
    }
}

// ---------------------------------------------------------------------------
// Grid barrier (96 CTAs, 1/SM, all co-resident)
// ---------------------------------------------------------------------------
__device__ __forceinline__ void grid_barrier(unsigned target) {
    __syncthreads();
    if (threadIdx.x == 0) {
        __threadfence();
        atomicAdd(&g_bar, 1u);
        unsigned v;
        do { v = *(volatile unsigned*)&g_bar; } while (v < target);
        __threadfence();
    }
    __syncthreads();
}

// ---------------------------------------------------------------------------
// Persistent kernel: all 128 GRU steps.
// Grid (48, 2), 512 threads = 16 warps, warp tile 16x24.
// 2-term bf16: C = Ah*W + Al*W  (A = h split hi/lo, W rounded once)
// Structure identical to Round-5 (2-stage, cp_wait<1>, 2 syncs/chunk).
// ---------------------------------------------------------------------------
__global__ __launch_bounds__(NTHREADS, 1) void persist_kernel(
    const float* __restrict__ context,
    const float* __restrict__ bias_ih,
    const float* __restrict__ bias_hh,
    const float* __restrict__ fc_w)
{
    extern __shared__ __align__(16) uint8_t smem[];
    __shared__ float sbr[JT], sbz[JT], sbni[JT], sbnh[JT], sfw[JT];

    const uint32_t sbase = smem_u32(smem);
    const int tid    = threadIdx.x;
    const int lane   = tid & 31;
    const int wid    = tid >> 5;
    const int warp_m = (wid & 7) * 16;     // 8 m-tiles of 16
    const int warp_n = (wid >> 3) * 24;    // 2 n-tiles of 24
    const int jb     = blockIdx.x;
    const int j0     = jb * JT;
    const int brow   = blockIdx.y * MTILE;

    // Epilogue ownership: thread = (batch row, j-quad)
    const int eb  = tid >> 2;              // 0..127
    const int ejq = (tid & 3) * 4;         // 0,4,8,12

    // ---- stage resident W (single bf16) into SMEM, SW128 swizzled ----
    for (int idx = tid; idx < NCHUNKS * NB * 8; idx += NTHREADS) {
        int ck  = idx / (NB * 8);
        int rem = idx - ck * (NB * 8);
        int r   = rem >> 3, cg = rem & 7;
        int wrow = (r >> 4) * HDIM + j0 + (r & 15);
        size_t so = (size_t)wrow * HDIM + ck * KCHUNK + cg * 8;
        uint32_t dst = (uint32_t)(ck * (NB * 128)) + SW128((uint32_t)(r * 128 + cg * 16));
        cp16(sbase + dst, g_wh + so);
    }
    cp_commit();   // W group

    if (tid < JT) {
        int j = j0 + tid;
        sbr[tid]  = bias_ih[j] + bias_hh[j];
        sbz[tid]  = bias_ih[HDIM + j] + bias_hh[HDIM + j];
        sbni[tid] = bias_ih[2 * HDIM + j];
        sbnh[tid] = bias_hh[2 * HDIM + j];
        sfw[tid]  = fc_w[j];
    }

    // fp32 h in registers: thread owns (brow+eb, j0+ejq..+3)
    float hreg[4];
    {
        const float* crow = context + (size_t)(brow + eb) * HDIM + j0 + ejq;
#pragma unroll
        for (int jj = 0; jj < 4; jj++) hreg[jj] = crow[jj];
    }
    __syncthreads();

    unsigned bar_target = 0;
    for (int t = 0; t < TSTEPS; t++) {
        const int rp = t & 1;
        const int wp = rp ^ 1;
        const __nv_bfloat16* __restrict__ hhi = g_hhi[rp];
        const __nv_bfloat16* __restrict__ hlo = g_hlo[rp];

        float acc[3][4];
#pragma unroll
        for (int ni = 0; ni < 3; ni++)
#pragma unroll
            for (int q = 0; q < 4; q++) acc[ni][q] = 0.0f;

        auto issueA = [&](int ck) {
            const int k0 = ck * KCHUNK;
            const uint32_t abase = sbase + AOFF + (uint32_t)(ck & 1) * ABUF;
#pragma unroll
            for (int idx = tid; idx < MTILE * 8; idx += NTHREADS) {  // 2 iters
                int r = idx >> 3, cg = idx & 7;
                uint32_t off = SW128((uint32_t)(r * 128 + cg * 16));
                size_t so = (size_t)(brow + r) * HDIM + k0 + cg * 8;
                cp16(abase + off,         hhi + so);
                cp16(abase + APART + off, hlo + so);
            }
            cp_commit();
        };

        auto compute = [&](int ck) {
            const uint32_t abase = sbase + AOFF + (uint32_t)(ck & 1) * ABUF;
            const uint32_t wbase = sbase + (uint32_t)(ck * (NB * 128));
#pragma unroll
            for (int ks = 0; ks < KCHUNK / 16; ks++) {
                const uint32_t kb = ks * 32;
                uint32_t ah[4], al[4], bw[3][2];
                {
                    uint32_t off = SW128(
                        (uint32_t)((warp_m + (lane & 15)) * 128) + kb +
                        ((lane >> 4) & 1) * 16);
                    ldsm_x4(ah, abase + off);
                    ldsm_x4(al, abase + APART + off);
                }
#pragma unroll
                for (int ni = 0; ni < 3; ni++) {
                    uint32_t off = SW128(
                        (uint32_t)((warp_n + ni * 8 + (lane & 7)) * 128) + kb +
                        ((lane >> 3) & 1) * 16);
                    ldsm_x2(bw[ni], wbase + off);
                }
#pragma unroll
                for (int ni = 0; ni < 3; ni++) {
                    mma_bf16(acc[ni], ah, bw[ni]);
                    mma_bf16(acc[ni], al, bw[ni]);
                }
            }
        };

        // ---- R5-style pipelined K loop: 2 stages, cp_wait<1> ----
        issueA(0);
        for (int ck = 0; ck < NCHUNKS; ck++) {
            if (ck + 1 < NCHUNKS) { issueA(ck + 1); cp_wait<1>(); }
            else                  { cp_wait<0>(); }
            __syncthreads();
            compute(ck);
            __syncthreads();
        }

        // ---- C to SMEM (aliases A buffers) ----
        float* Csm = (float*)(smem + AOFF);
        {
            const int r0 = lane >> 2, cpn = (lane & 3) * 2;
#pragma unroll
            for (int ni = 0; ni < 3; ni++) {
                int row = warp_m + r0;
                int col = warp_n + ni * 8 + cpn;
                Csm[row * CSTRIDE + col]           = acc[ni][0];
                Csm[row * CSTRIDE + col + 1]       = acc[ni][1];
                Csm[(row + 8) * CSTRIDE + col]     = acc[ni][2];
                Csm[(row + 8) * CSTRIDE + col + 1] = acc[ni][3];
            }
        }
        __syncthreads();

        // ---- gate epilogue: thread = (batch row, j-quad) ----
        {
            const int b = brow + eb;
            __nv_bfloat16* __restrict__ hih = g_hhi[wp] + (size_t)b * HDIM + j0 + ejq;
            __nv_bfloat16* __restrict__ hil = g_hlo[wp] + (size_t)b * HDIM + j0 + ejq;
            const float* crow = Csm + eb * CSTRIDE;

            float part = 0.0f;
#pragma unroll
            for (int q = 0; q < 4; q++) {
                const int jj = ejq + q;
                float rawr = crow[jj];
                float rawz = crow[JT + jj];
                float rawn = crow[2 * JT + jj];

                float rg = 1.0f / (1.0f + expf(-(sbr[jj] + rawr)));
                float zg = 1.0f / (1.0f + expf(-(sbz[jj] + rawz)));
                float ng = tanhf(sbni[jj] + rg * (rawn + sbnh[jj]));
                float hn = (1.0f - zg) * ng + zg * hreg[q];

                hreg[q] = hn;
                __nv_bfloat16 hi = __float2bfloat16_rn(hn);
                hih[q] = hi;
                hil[q] = __float2bfloat16_rn(hn - __bfloat162float(hi));
                part += hn * sfw[jj];
            }
            part += __shfl_xor_sync(0xFFFFFFFFu, part, 1);
            part += __shfl_xor_sync(0xFFFFFFFFu, part, 2);
            if ((tid & 3) == 0)
                g_dotp[(size_t)t * NJB * BSZ + jb * BSZ + b] = part;
        }
        __syncthreads();   // protect Csm/A-buffer reuse by next step's issueA(0)

        bar_target += NCTA;
        if (t + 1 < TSTEPS) grid_barrier(bar_target);
    }
}

// ---------------------------------------------------------------------------
// Finalize: dot = fixed-order sum of 48 partials, softplus, scan, normalize
// ---------------------------------------------------------------------------
__device__ __forceinline__ float softplusf_(float x) {
    return (x > 0.0f) ? (x + log1pf(expf(-x))) : log1pf(expf(x));
}

__global__ __launch_bounds__(TSTEPS) void finalize_kernel(
    const int* __restrict__ num_pred,
    const float* __restrict__ fc_b,
    float* __restrict__ out)
{
    __shared__ float s[TSTEPS];
    const int b = blockIdx.x;
    const int t = threadIdx.x;

    float dot = fc_b[0];
    const float* p = g_dotp + (size_t)t * NJB * BSZ + b;
#pragma unroll
    for (int jbk = 0; jbk < NJB; jbk++) dot += p[jbk * BSZ];
    s[t] = softplusf_(dot);
    __syncthreads();

#pragma unroll
    for (int off = 1; off < TSTEPS; off <<= 1) {
        float v = (t >= off) ? s[t - off] : 0.0f;
        __syncthreads();
        s[t] += v;
        __syncthreads();
    }

    const int n = num_pred[b];
    int idx = n - 1;
    if (idx < 0) idx = 0;
    if (idx > TSTEPS - 1) idx = TSTEPS - 1;
    const float last = s[idx] + 1e-6f;

    float* orow = out + (size_t)b * (TSTEPS + 2);
    float val;
    if (t < n)       val = s[t] / last;
    else if (t == n) val = 1.0f;
    else             val = 0.0f;
    orow[t + 1] = val;

    if (t == 0) {
        orow[0] = 0.0f;
        orow[TSTEPS + 1] = (n == TSTEPS) ? 1.0f : 0.0f;
    }
}

// ---------------------------------------------------------------------------
// Launch. Inputs: 0 context 1 weight_ih(unused) 2 weight_hh 3 bias_ih
//                 4 bias_hh 5 fc_w 6 fc_b 7 num_pred_list 8 max_steps
// ---------------------------------------------------------------------------
extern "C" void kernel_launch(void* const* d_in, const int* in_sizes, int n_in,
                              void* d_out, int out_size)
{
    const float* context  = (const float*)d_in[0];
    const float* Whh      = (const float*)d_in[2];
    const float* bias_ih  = (const float*)d_in[3];
    const float* bias_hh  = (const float*)d_in[4];
    const float* fc_w     = (const float*)d_in[5];
    const float* fc_b     = (const float*)d_in[6];
    const int*   num_pred = (const int*)d_in[7];
    float*       out      = (float*)d_out;

    static bool attr_set = false;
    if (!attr_set) {
        cudaFuncSetAttribute(persist_kernel,
                             cudaFuncAttributeMaxDynamicSharedMemorySize, SMEM_DYN);
        attr_set = true;
    }

    prep_w_kernel<<<(H3 * HDIM + 255) / 256, 256>>>(Whh);
    prep_h_kernel<<<(BSZ * HDIM + 255) / 256, 256>>>(context);

    dim3 grid(NJB, BSZ / MTILE);  // (48, 2) = 96 CTAs, 1 per SM
    persist_kernel<<<grid, NTHREADS, SMEM_DYN>>>(context, bias_ih, bias_hh, fc_w);

    finalize_kernel<<<BSZ, TSTEPS>>>(num_pred, fc_b, out);
}

// round 9
// speedup vs baseline: 2.1026x; 1.3520x over previous
#include <cuda_runtime.h>
#include <cuda_bf16.h>
#include <math.h>
#include <stdint.h>

// Problem constants
#define BSZ    256
#define HDIM   768
#define H3     2304
#define TSTEPS 128

// Tiling
#define JT       24               // j-columns per CTA (per gate)
#define NB       72               // 3 gates * JT rows of W per CTA
#define MTILE    64               // batch rows per CTA
#define NKC      12               // 64-wide k-chunks
#define NPAIR    6                // pipeline stages process 2 chunks each
#define NTHREADS 384              // 12 warps
#define NJB      (HDIM / JT)      // 32
#define NCTA     128              // 32 x 4, all resident (1 CTA/SM)

// Dynamic SMEM layout (bytes)
//   W resident (single bf16): [chunk(12)][row(72)][128B], SW128 = 110592
//   A stages: [buf(2)][part hi/lo][sub(2)][row(64)][128B]
#define WCH      (NB * 128)                    // 9216 per chunk
#define WBYTES   (NKC * WCH)                   // 110592
#define AOFF     WBYTES
#define ASUB     (MTILE * 128)                 // 8192
#define APART    (2 * ASUB)                    // 16384 (2 sub-chunks)
#define ABUF     (2 * APART)                   // 32768 per stage
#define SMEM_DYN (AOFF + 2 * ABUF)             // 176128
#define CSTRIDE  73                            // fp32 C row stride in epilogue

// ---------------------------------------------------------------------------
// Device globals
// ---------------------------------------------------------------------------
__device__ __align__(16) __nv_bfloat16 g_hhi[2][BSZ * HDIM];
__device__ __align__(16) __nv_bfloat16 g_hlo[2][BSZ * HDIM];
__device__ __align__(16) __nv_bfloat16 g_wh[H3 * HDIM];    // single bf16 W
__device__ float    g_dotp[TSTEPS * NJB * BSZ];
__device__ unsigned g_bar;

// ---------------------------------------------------------------------------
// PTX helpers (baseline sm_80/90 features only — NO tcgen05)
// ---------------------------------------------------------------------------
__device__ __forceinline__ uint32_t smem_u32(const void* p) {
    uint32_t a;
    asm("{ .reg .u64 t; cvta.to.shared.u64 t, %1; cvt.u32.u64 %0, t; }"
        : "=r"(a) : "l"(p));
    return a;
}
__device__ __forceinline__ void cp16(uint32_t d, const void* s) {
    asm volatile("cp.async.cg.shared.global [%0], [%1], 16;" :: "r"(d), "l"(s));
}
__device__ __forceinline__ void cp_commit() {
    asm volatile("cp.async.commit_group;" ::: "memory");
}
template <int N>
__device__ __forceinline__ void cp_wait() {
    asm volatile("cp.async.wait_group %0;" :: "n"(N) : "memory");
}
__device__ __forceinline__ void ldsm_x4(uint32_t* r, uint32_t a) {
    asm volatile("ldmatrix.sync.aligned.m8n8.x4.shared.b16 {%0,%1,%2,%3}, [%4];"
                 : "=r"(r[0]), "=r"(r[1]), "=r"(r[2]), "=r"(r[3]) : "r"(a));
}
__device__ __forceinline__ void ldsm_x2(uint32_t* r, uint32_t a) {
    asm volatile("ldmatrix.sync.aligned.m8n8.x2.shared.b16 {%0,%1}, [%2];"
                 : "=r"(r[0]), "=r"(r[1]) : "r"(a));
}
__device__ __forceinline__ void mma_bf16(float* c, const uint32_t* a, const uint32_t* b) {
    asm volatile(
        "mma.sync.aligned.m16n8k16.row.col.f32.bf16.bf16.f32 "
        "{%0,%1,%2,%3}, {%4,%5,%6,%7}, {%8,%9}, {%0,%1,%2,%3};"
        : "+f"(c[0]), "+f"(c[1]), "+f"(c[2]), "+f"(c[3])
        : "r"(a[0]), "r"(a[1]), "r"(a[2]), "r"(a[3]), "r"(b[0]), "r"(b[1]));
}
#define SW128(o) ((o) ^ (((o) >> 3) & 0x70))

// ---------------------------------------------------------------------------
// Prep kernels
// ---------------------------------------------------------------------------
__global__ void prep_w_kernel(const float* __restrict__ W) {
    int i = blockIdx.x * blockDim.x + threadIdx.x;
    if (i < H3 * HDIM) g_wh[i] = __float2bfloat16_rn(W[i]);
}
__global__ void prep_h_kernel(const float* __restrict__ ctx) {
    int i = blockIdx.x * blockDim.x + threadIdx.x;
    if (i == 0) g_bar = 0u;
    if (i < BSZ * HDIM) {
        float v = ctx[i];
        __nv_bfloat16 hi = __float2bfloat16_rn(v);
        g_hhi[0][i] = hi;
        g_hlo[0][i] = __float2bfloat16_rn(v - __bfloat162float(hi));
    }
}

// ---------------------------------------------------------------------------
// Grid barrier (128 CTAs, 1/SM, all co-resident)
// ---------------------------------------------------------------------------
__device__ __forceinline__ void grid_barrier(unsigned target) {
    __syncthreads();
    if (threadIdx.x == 0) {
        __threadfence();
        atomicAdd(&g_bar, 1u);
        unsigned v;
        do { v = *(volatile unsigned*)&g_bar; } while (v < target);
        __threadfence();
    }
    __syncthreads();
}

// ---------------------------------------------------------------------------
// Persistent kernel: all 128 GRU steps.
// Grid (32, 4), 384 threads = 12 warps, warp tile 16x24 over CTA tile 64x72.
// 2-term bf16: C = Ah*W + Al*W. 2-stage pipeline, 2 k-chunks per stage.
// ---------------------------------------------------------------------------
__global__ __launch_bounds__(NTHREADS, 1) void persist_kernel(
    const float* __restrict__ context,
    const float* __restrict__ bias_ih,
    const float* __restrict__ bias_hh,
    const float* __restrict__ fc_w)
{
    extern __shared__ __align__(16) uint8_t smem[];
    __shared__ float sbr[JT], sbz[JT], sbni[JT], sbnh[JT], sfw[JT];

    const uint32_t sbase = smem_u32(smem);
    const int tid    = threadIdx.x;
    const int lane   = tid & 31;
    const int wid    = tid >> 5;
    const int warp_m = (wid & 3) * 16;     // 4 m-tiles of 16 (M=64)
    const int warp_n = (wid >> 2) * 24;    // 3 n-tiles of 24 (N=72)
    const int jb     = blockIdx.x;
    const int j0     = jb * JT;
    const int brow   = blockIdx.y * MTILE;

    // Epilogue ownership: threads 0..255 = (batch row, j-group of 6)
    const int eb  = tid >> 2;              // 0..63 (for tid<256)
    const int ejq = (tid & 3) * 6;         // 0,6,12,18

    // ---- stage resident W (single bf16) into SMEM, SW128 swizzled ----
    for (int idx = tid; idx < NKC * NB * 8; idx += NTHREADS) {
        int ck  = idx / (NB * 8);
        int rem = idx - ck * (NB * 8);
        int r   = rem >> 3, cg = rem & 7;
        int wrow = (r / JT) * HDIM + j0 + (r % JT);
        size_t so = (size_t)wrow * HDIM + ck * 64 + cg * 8;
        uint32_t dst = (uint32_t)(ck * WCH) + SW128((uint32_t)(r * 128 + cg * 16));
        cp16(sbase + dst, g_wh + so);
    }
    cp_commit();   // W group

    if (tid < JT) {
        int j = j0 + tid;
        sbr[tid]  = bias_ih[j] + bias_hh[j];
        sbz[tid]  = bias_ih[HDIM + j] + bias_hh[HDIM + j];
        sbni[tid] = bias_ih[2 * HDIM + j];
        sbnh[tid] = bias_hh[2 * HDIM + j];
        sfw[tid]  = fc_w[j];
    }

    // fp32 h in registers: thread (tid<256) owns (brow+eb, j0+ejq..+5)
    float hreg[6];
    if (tid < 256) {
        const float* crow = context + (size_t)(brow + eb) * HDIM + j0 + ejq;
#pragma unroll
        for (int jj = 0; jj < 6; jj++) hreg[jj] = crow[jj];
    }
    __syncthreads();

    unsigned bar_target = 0;
    for (int t = 0; t < TSTEPS; t++) {
        const int rp = t & 1;
        const int wp = rp ^ 1;
        const __nv_bfloat16* __restrict__ hhi = g_hhi[rp];
        const __nv_bfloat16* __restrict__ hlo = g_hlo[rp];

        float acc[3][4];
#pragma unroll
        for (int ni = 0; ni < 3; ni++)
#pragma unroll
            for (int q = 0; q < 4; q++) acc[ni][q] = 0.0f;

        // stage pair p: k-chunks 2p, 2p+1 (128 K elems)
        auto issueA = [&](int p) {
            const uint32_t abase = sbase + AOFF + (uint32_t)(p & 1) * ABUF;
            const int k0 = p * 128;
            for (int idx = tid; idx < MTILE * 16; idx += NTHREADS) {  // ~2.7 iters
                int r = idx >> 4, cg = idx & 15;
                int sub = cg >> 3, cgi = cg & 7;
                uint32_t off = (uint32_t)(sub * ASUB) +
                               SW128((uint32_t)(r * 128 + cgi * 16));
                size_t so = (size_t)(brow + r) * HDIM + k0 + sub * 64 + cgi * 8;
                cp16(abase + off,         hhi + so);
                cp16(abase + APART + off, hlo + so);
            }
            cp_commit();
        };

        auto compute = [&](int p) {
            const uint32_t abase = sbase + AOFF + (uint32_t)(p & 1) * ABUF;
#pragma unroll
            for (int sub = 0; sub < 2; sub++) {
                const uint32_t asb  = abase + sub * ASUB;
                const uint32_t wbase = sbase + (uint32_t)((2 * p + sub) * WCH);
#pragma unroll
                for (int ks = 0; ks < 4; ks++) {
                    const uint32_t kb = ks * 32;
                    uint32_t ah[4], al[4], bw[3][2];
                    {
                        uint32_t off = SW128(
                            (uint32_t)((warp_m + (lane & 15)) * 128) + kb +
                            ((lane >> 4) & 1) * 16);
                        ldsm_x4(ah, asb + off);
                        ldsm_x4(al, asb + APART + off);
                    }
#pragma unroll
                    for (int ni = 0; ni < 3; ni++) {
                        uint32_t off = SW128(
                            (uint32_t)((warp_n + ni * 8 + (lane & 7)) * 128) + kb +
                            ((lane >> 3) & 1) * 16);
                        ldsm_x2(bw[ni], wbase + off);
                    }
#pragma unroll
                    for (int ni = 0; ni < 3; ni++) {
                        mma_bf16(acc[ni], ah, bw[ni]);
                        mma_bf16(acc[ni], al, bw[ni]);
                    }
                }
            }
        };

        // ---- pipelined loop: 6 stage-pairs, 2 syncs each ----
        issueA(0);
        for (int p = 0; p < NPAIR; p++) {
            if (p + 1 < NPAIR) { issueA(p + 1); cp_wait<1>(); }
            else               { cp_wait<0>(); }
            __syncthreads();
            compute(p);
            __syncthreads();
        }

        // ---- C to SMEM (aliases A buffers) ----
        float* Csm = (float*)(smem + AOFF);
        {
            const int r0 = lane >> 2, cpn = (lane & 3) * 2;
#pragma unroll
            for (int ni = 0; ni < 3; ni++) {
                int row = warp_m + r0;
                int col = warp_n + ni * 8 + cpn;
                Csm[row * CSTRIDE + col]           = acc[ni][0];
                Csm[row * CSTRIDE + col + 1]       = acc[ni][1];
                Csm[(row + 8) * CSTRIDE + col]     = acc[ni][2];
                Csm[(row + 8) * CSTRIDE + col + 1] = acc[ni][3];
            }
        }
        __syncthreads();

        // ---- gate epilogue: threads 0..255 = (row, j-group of 6) ----
        if (tid < 256) {
            const int b = brow + eb;
            __nv_bfloat16* __restrict__ hih = g_hhi[wp] + (size_t)b * HDIM + j0 + ejq;
            __nv_bfloat16* __restrict__ hil = g_hlo[wp] + (size_t)b * HDIM + j0 + ejq;
            const float* crow = Csm + eb * CSTRIDE;

            float part = 0.0f;
#pragma unroll
            for (int q = 0; q < 6; q++) {
                const int jj = ejq + q;
                float rawr = crow[jj];
                float rawz = crow[JT + jj];
                float rawn = crow[2 * JT + jj];

                float rg = 1.0f / (1.0f + expf(-(sbr[jj] + rawr)));
                float zg = 1.0f / (1.0f + expf(-(sbz[jj] + rawz)));
                float ng = tanhf(sbni[jj] + rg * (rawn + sbnh[jj]));
                float hn = (1.0f - zg) * ng + zg * hreg[q];

                hreg[q] = hn;
                __nv_bfloat16 hi = __float2bfloat16_rn(hn);
                hih[q] = hi;
                hil[q] = __float2bfloat16_rn(hn - __bfloat162float(hi));
                part += hn * sfw[jj];
            }
            part += __shfl_xor_sync(0xFFFFFFFFu, part, 1);
            part += __shfl_xor_sync(0xFFFFFFFFu, part, 2);
            if ((tid & 3) == 0)
                g_dotp[(size_t)t * NJB * BSZ + jb * BSZ + b] = part;
        }
        __syncthreads();   // protect Csm/A-buffer reuse by next step's issueA(0)

        bar_target += NCTA;
        if (t + 1 < TSTEPS) grid_barrier(bar_target);
    }
}

// ---------------------------------------------------------------------------
// Finalize: dot = fixed-order sum of 32 partials, softplus, scan, normalize
// ---------------------------------------------------------------------------
__device__ __forceinline__ float softplusf_(float x) {
    return (x > 0.0f) ? (x + log1pf(expf(-x))) : log1pf(expf(x));
}

__global__ __launch_bounds__(TSTEPS) void finalize_kernel(
    const int* __restrict__ num_pred,
    const float* __restrict__ fc_b,
    float* __restrict__ out)
{
    __shared__ float s[TSTEPS];
    const int b = blockIdx.x;
    const int t = threadIdx.x;

    float dot = fc_b[0];
    const float* p = g_dotp + (size_t)t * NJB * BSZ + b;
#pragma unroll
    for (int jbk = 0; jbk < NJB; jbk++) dot += p[jbk * BSZ];
    s[t] = softplusf_(dot);
    __syncthreads();

#pragma unroll
    for (int off = 1; off < TSTEPS; off <<= 1) {
        float v = (t >= off) ? s[t - off] : 0.0f;
        __syncthreads();
        s[t] += v;
        __syncthreads();
    }

    const int n = num_pred[b];
    int idx = n - 1;
    if (idx < 0) idx = 0;
    if (idx > TSTEPS - 1) idx = TSTEPS - 1;
    const float last = s[idx] + 1e-6f;

    float* orow = out + (size_t)b * (TSTEPS + 2);
    float val;
    if (t < n)       val = s[t] / last;
    else if (t == n) val = 1.0f;
    else             val = 0.0f;
    orow[t + 1] = val;

    if (t == 0) {
        orow[0] = 0.0f;
        orow[TSTEPS + 1] = (n == TSTEPS) ? 1.0f : 0.0f;
    }
}

// ---------------------------------------------------------------------------
// Launch. Inputs: 0 context 1 weight_ih(unused) 2 weight_hh 3 bias_ih
//                 4 bias_hh 5 fc_w 6 fc_b 7 num_pred_list 8 max_steps
// ---------------------------------------------------------------------------
extern "C" void kernel_launch(void* const* d_in, const int* in_sizes, int n_in,
                              void* d_out, int out_size)
{
    const float* context  = (const float*)d_in[0];
    const float* Whh      = (const float*)d_in[2];
    const float* bias_ih  = (const float*)d_in[3];
    const float* bias_hh  = (const float*)d_in[4];
    const float* fc_w     = (const float*)d_in[5];
    const float* fc_b     = (const float*)d_in[6];
    const int*   num_pred = (const int*)d_in[7];
    float*       out      = (float*)d_out;

    static bool attr_set = false;
    if (!attr_set) {
        cudaFuncSetAttribute(persist_kernel,
                             cudaFuncAttributeMaxDynamicSharedMemorySize, SMEM_DYN);
        attr_set = true;
    }

    prep_w_kernel<<<(H3 * HDIM + 255) / 256, 256>>>(Whh);
    prep_h_kernel<<<(BSZ * HDIM + 255) / 256, 256>>>(context);

    dim3 grid(NJB, BSZ / MTILE);  // (32, 4) = 128 CTAs, 1 per SM
    persist_kernel<<<grid, NTHREADS, SMEM_DYN>>>(context, bias_ih, bias_hh, fc_w);

    finalize_kernel<<<BSZ, TSTEPS>>>(num_pred, fc_b, out);
}

// round 10
// speedup vs baseline: 2.1342x; 1.0150x over previous
#include <cuda_runtime.h>
#include <cuda_bf16.h>
#include <math.h>
#include <stdint.h>

// Problem constants
#define BSZ    256
#define HDIM   768
#define H3     2304
#define TSTEPS 128

// Tiling
#define JT       24               // j-columns per CTA (per gate)
#define NB       72               // 3 gates * JT rows of W per CTA
#define MTILE    64               // batch rows per CTA
#define NKC      12               // 64-wide k-chunks
#define NPAIR    6                // pipeline iterations (2 k-chunks each)
#define NSTAGE   3                // A ring depth
#define NTHREADS 384              // 12 warps
#define NJB      (HDIM / JT)      // 32
#define NGRP     32               // CTAs per barrier group (one batch-tile row)

// Dynamic SMEM layout (bytes)
//   W resident (single bf16): [chunk(12)][row(72)][128B], SW128 = 110592
//   A ring: [stage(3)][part hi/lo][sub(2)][row(64)][128B]
#define WCH      (NB * 128)                    // 9216 per chunk
#define WBYTES   (NKC * WCH)                   // 110592
#define AOFF     WBYTES
#define ASUB     (MTILE * 128)                 // 8192
#define APART    (2 * ASUB)                    // 16384 (2 sub-chunks)
#define ABUF     (2 * APART)                   // 32768 per stage
#define SMEM_DYN (AOFF + NSTAGE * ABUF)        // 208896
#define CSTRIDE  73                            // fp32 C row stride in epilogue

// ---------------------------------------------------------------------------
// Device globals
// ---------------------------------------------------------------------------
__device__ __align__(16) __nv_bfloat16 g_hhi[2][BSZ * HDIM];
__device__ __align__(16) __nv_bfloat16 g_hlo[2][BSZ * HDIM];
__device__ __align__(16) __nv_bfloat16 g_wh[H3 * HDIM];    // single bf16 W
__device__ float    g_dotp[TSTEPS * NJB * BSZ];
__device__ unsigned g_barg[4 * 32];   // 4 group counters, 128B apart

// ---------------------------------------------------------------------------
// PTX helpers (baseline sm_80/90 features only — NO tcgen05)
// ---------------------------------------------------------------------------
__device__ __forceinline__ uint32_t smem_u32(const void* p) {
    uint32_t a;
    asm("{ .reg .u64 t; cvta.to.shared.u64 t, %1; cvt.u32.u64 %0, t; }"
        : "=r"(a) : "l"(p));
    return a;
}
__device__ __forceinline__ void cp16(uint32_t d, const void* s) {
    asm volatile("cp.async.cg.shared.global [%0], [%1], 16;" :: "r"(d), "l"(s));
}
__device__ __forceinline__ void cp_commit() {
    asm volatile("cp.async.commit_group;" ::: "memory");
}
template <int N>
__device__ __forceinline__ void cp_wait() {
    asm volatile("cp.async.wait_group %0;" :: "n"(N) : "memory");
}
__device__ __forceinline__ void ldsm_x4(uint32_t* r, uint32_t a) {
    asm volatile("ldmatrix.sync.aligned.m8n8.x4.shared.b16 {%0,%1,%2,%3}, [%4];"
                 : "=r"(r[0]), "=r"(r[1]), "=r"(r[2]), "=r"(r[3]) : "r"(a));
}
__device__ __forceinline__ void ldsm_x2(uint32_t* r, uint32_t a) {
    asm volatile("ldmatrix.sync.aligned.m8n8.x2.shared.b16 {%0,%1}, [%2];"
                 : "=r"(r[0]), "=r"(r[1]) : "r"(a));
}
__device__ __forceinline__ void mma_bf16(float* c, const uint32_t* a, const uint32_t* b) {
    asm volatile(
        "mma.sync.aligned.m16n8k16.row.col.f32.bf16.bf16.f32 "
        "{%0,%1,%2,%3}, {%4,%5,%6,%7}, {%8,%9}, {%0,%1,%2,%3};"
        : "+f"(c[0]), "+f"(c[1]), "+f"(c[2]), "+f"(c[3])
        : "r"(a[0]), "r"(a[1]), "r"(a[2]), "r"(a[3]), "r"(b[0]), "r"(b[1]));
}
#define SW128(o) ((o) ^ (((o) >> 3) & 0x70))

// ---------------------------------------------------------------------------
// Prep kernels
// ---------------------------------------------------------------------------
__global__ void prep_w_kernel(const float* __restrict__ W) {
    int i = blockIdx.x * blockDim.x + threadIdx.x;
    if (i < H3 * HDIM) g_wh[i] = __float2bfloat16_rn(W[i]);
}
__global__ void prep_h_kernel(const float* __restrict__ ctx) {
    int i = blockIdx.x * blockDim.x + threadIdx.x;
    if (i < 4 * 32) g_barg[i] = 0u;
    if (i < BSZ * HDIM) {
        float v = ctx[i];
        __nv_bfloat16 hi = __float2bfloat16_rn(v);
        g_hhi[0][i] = hi;
        g_hlo[0][i] = __float2bfloat16_rn(v - __bfloat162float(hi));
    }
}

// ---------------------------------------------------------------------------
// Group barrier: 32 CTAs sharing one batch-tile row (all co-resident)
// ---------------------------------------------------------------------------
__device__ __forceinline__ void group_barrier(unsigned* ctr, unsigned target) {
    __syncthreads();
    if (threadIdx.x == 0) {
        __threadfence();
        atomicAdd(ctr, 1u);
        unsigned v;
        do { v = *(volatile unsigned*)ctr; } while (v < target);
        __threadfence();
    }
    __syncthreads();
}

// ---------------------------------------------------------------------------
// Persistent kernel: all 128 GRU steps.
// Grid (32, 4), 384 threads = 12 warps, warp tile 16x24 over CTA tile 64x72.
// 2-term bf16: C = Ah*W + Al*W. 3-stage A ring, 1 sync per pair-stage.
// ---------------------------------------------------------------------------
__global__ __launch_bounds__(NTHREADS, 1) void persist_kernel(
    const float* __restrict__ context,
    const float* __restrict__ bias_ih,
    const float* __restrict__ bias_hh,
    const float* __restrict__ fc_w)
{
    extern __shared__ __align__(16) uint8_t smem[];
    __shared__ float sbr[JT], sbz[JT], sbni[JT], sbnh[JT], sfw[JT];

    const uint32_t sbase = smem_u32(smem);
    const int tid    = threadIdx.x;
    const int lane   = tid & 31;
    const int wid    = tid >> 5;
    const int warp_m = (wid & 3) * 16;     // 4 m-tiles of 16 (M=64)
    const int warp_n = (wid >> 2) * 24;    // 3 n-tiles of 24 (N=72)
    const int jb     = blockIdx.x;
    const int j0     = jb * JT;
    const int brow   = blockIdx.y * MTILE;
    unsigned* bctr   = &g_barg[blockIdx.y * 32];

    // Epilogue ownership: threads 0..255 = (batch row, j-group of 6)
    const int eb  = tid >> 2;              // 0..63 (for tid<256)
    const int ejq = (tid & 3) * 6;         // 0,6,12,18

    // ---- stage resident W (single bf16) into SMEM, SW128 swizzled ----
    for (int idx = tid; idx < NKC * NB * 8; idx += NTHREADS) {
        int ck  = idx / (NB * 8);
        int rem = idx - ck * (NB * 8);
        int r   = rem >> 3, cg = rem & 7;
        int wrow = (r / JT) * HDIM + j0 + (r % JT);
        size_t so = (size_t)wrow * HDIM + ck * 64 + cg * 8;
        uint32_t dst = (uint32_t)(ck * WCH) + SW128((uint32_t)(r * 128 + cg * 16));
        cp16(sbase + dst, g_wh + so);
    }
    cp_commit();   // W group

    if (tid < JT) {
        int j = j0 + tid;
        sbr[tid]  = bias_ih[j] + bias_hh[j];
        sbz[tid]  = bias_ih[HDIM + j] + bias_hh[HDIM + j];
        sbni[tid] = bias_ih[2 * HDIM + j];
        sbnh[tid] = bias_hh[2 * HDIM + j];
        sfw[tid]  = fc_w[j];
    }

    // fp32 h in registers: thread (tid<256) owns (brow+eb, j0+ejq..+5)
    float hreg[6];
    if (tid < 256) {
        const float* crow = context + (size_t)(brow + eb) * HDIM + j0 + ejq;
#pragma unroll
        for (int jj = 0; jj < 6; jj++) hreg[jj] = crow[jj];
    }
    __syncthreads();

    unsigned bar_target = 0;
    for (int t = 0; t < TSTEPS; t++) {
        const int rp = t & 1;
        const int wp = rp ^ 1;
        const __nv_bfloat16* __restrict__ hhi = g_hhi[rp];
        const __nv_bfloat16* __restrict__ hlo = g_hlo[rp];

        float acc[3][4];
#pragma unroll
        for (int ni = 0; ni < 3; ni++)
#pragma unroll
            for (int q = 0; q < 4; q++) acc[ni][q] = 0.0f;

        // pair-stage p covers k-chunks 2p, 2p+1 (128 K elems); stage = p % 3
        auto issueA = [&](int p) {
            const uint32_t abase = sbase + AOFF + (uint32_t)(p % NSTAGE) * ABUF;
            const int k0 = p * 128;
            for (int idx = tid; idx < MTILE * 16; idx += NTHREADS) {  // ~2.7 iters
                int r = idx >> 4, cg = idx & 15;
                int sub = cg >> 3, cgi = cg & 7;
                uint32_t off = (uint32_t)(sub * ASUB) +
                               SW128((uint32_t)(r * 128 + cgi * 16));
                size_t so = (size_t)(brow + r) * HDIM + k0 + sub * 64 + cgi * 8;
                cp16(abase + off,         hhi + so);
                cp16(abase + APART + off, hlo + so);
            }
            cp_commit();
        };

        auto compute = [&](int p) {
            const uint32_t abase = sbase + AOFF + (uint32_t)(p % NSTAGE) * ABUF;
#pragma unroll
            for (int sub = 0; sub < 2; sub++) {
                const uint32_t asb   = abase + sub * ASUB;
                const uint32_t wbase = sbase + (uint32_t)((2 * p + sub) * WCH);
#pragma unroll
                for (int ks = 0; ks < 4; ks++) {
                    const uint32_t kb = ks * 32;
                    uint32_t ah[4], al[4], bw[3][2];
                    {
                        uint32_t off = SW128(
                            (uint32_t)((warp_m + (lane & 15)) * 128) + kb +
                            ((lane >> 4) & 1) * 16);
                        ldsm_x4(ah, asb + off);
                        ldsm_x4(al, asb + APART + off);
                    }
#pragma unroll
                    for (int ni = 0; ni < 3; ni++) {
                        uint32_t off = SW128(
                            (uint32_t)((warp_n + ni * 8 + (lane & 7)) * 128) + kb +
                            ((lane >> 3) & 1) * 16);
                        ldsm_x2(bw[ni], wbase + off);
                    }
#pragma unroll
                    for (int ni = 0; ni < 3; ni++) {
                        mma_bf16(acc[ni], ah, bw[ni]);
                        mma_bf16(acc[ni], al, bw[ni]);
                    }
                }
            }
        };

        // ---- 3-stage pipelined loop: 1 sync per pair-stage ----
        issueA(0);
        issueA(1);
        for (int p = 0; p < NPAIR; p++) {
            if (p == NPAIR - 1) cp_wait<0>();
            else                cp_wait<1>();
            __syncthreads();
            if (p + 2 < NPAIR) issueA(p + 2);
            compute(p);
        }

        // ---- C to SMEM (stage 0 region; last read of stage 0 was compute(3),
        //      all threads past it via p=4,5 syncs) ----
        float* Csm = (float*)(smem + AOFF);
        {
            const int r0 = lane >> 2, cpn = (lane & 3) * 2;
#pragma unroll
            for (int ni = 0; ni < 3; ni++) {
                int row = warp_m + r0;
                int col = warp_n + ni * 8 + cpn;
                Csm[row * CSTRIDE + col]           = acc[ni][0];
                Csm[row * CSTRIDE + col + 1]       = acc[ni][1];
                Csm[(row + 8) * CSTRIDE + col]     = acc[ni][2];
                Csm[(row + 8) * CSTRIDE + col + 1] = acc[ni][3];
            }
        }
        __syncthreads();

        // ---- gate epilogue: threads 0..255 = (row, j-group of 6) ----
        if (tid < 256) {
            const int b = brow + eb;
            __nv_bfloat16* __restrict__ hih = g_hhi[wp] + (size_t)b * HDIM + j0 + ejq;
            __nv_bfloat16* __restrict__ hil = g_hlo[wp] + (size_t)b * HDIM + j0 + ejq;
            const float* crow = Csm + eb * CSTRIDE;

            float part = 0.0f;
#pragma unroll
            for (int q = 0; q < 6; q++) {
                const int jj = ejq + q;
                float rawr = crow[jj];
                float rawz = crow[JT + jj];
                float rawn = crow[2 * JT + jj];

                float rg = 1.0f / (1.0f + expf(-(sbr[jj] + rawr)));
                float zg = 1.0f / (1.0f + expf(-(sbz[jj] + rawz)));
                float ng = tanhf(sbni[jj] + rg * (rawn + sbnh[jj]));
                float hn = (1.0f - zg) * ng + zg * hreg[q];

                hreg[q] = hn;
                __nv_bfloat16 hi = __float2bfloat16_rn(hn);
                hih[q] = hi;
                hil[q] = __float2bfloat16_rn(hn - __bfloat162float(hi));
                part += hn * sfw[jj];
            }
            part += __shfl_xor_sync(0xFFFFFFFFu, part, 1);
            part += __shfl_xor_sync(0xFFFFFFFFu, part, 2);
            if ((tid & 3) == 0)
                g_dotp[(size_t)t * NJB * BSZ + jb * BSZ + b] = part;
        }

        // group barrier (leading __syncthreads also protects Csm reuse)
        bar_target += NGRP;
        if (t + 1 < TSTEPS) group_barrier(bctr, bar_target);
    }
}

// ---------------------------------------------------------------------------
// Finalize: dot = fixed-order sum of 32 partials, softplus, scan, normalize
// ---------------------------------------------------------------------------
__device__ __forceinline__ float softplusf_(float x) {
    return (x > 0.0f) ? (x + log1pf(expf(-x))) : log1pf(expf(x));
}

__global__ __launch_bounds__(TSTEPS) void finalize_kernel(
    const int* __restrict__ num_pred,
    const float* __restrict__ fc_b,
    float* __restrict__ out)
{
    __shared__ float s[TSTEPS];
    const int b = blockIdx.x;
    const int t = threadIdx.x;

    float dot = fc_b[0];
    const float* p = g_dotp + (size_t)t * NJB * BSZ + b;
#pragma unroll
    for (int jbk = 0; jbk < NJB; jbk++) dot += p[jbk * BSZ];
    s[t] = softplusf_(dot);
    __syncthreads();

#pragma unroll
    for (int off = 1; off < TSTEPS; off <<= 1) {
        float v = (t >= off) ? s[t - off] : 0.0f;
        __syncthreads();
        s[t] += v;
        __syncthreads();
    }

    const int n = num_pred[b];
    int idx = n - 1;
    if (idx < 0) idx = 0;
    if (idx > TSTEPS - 1) idx = TSTEPS - 1;
    const float last = s[idx] + 1e-6f;

    float* orow = out + (size_t)b * (TSTEPS + 2);
    float val;
    if (t < n)       val = s[t] / last;
    else if (t == n) val = 1.0f;
    else             val = 0.0f;
    orow[t + 1] = val;

    if (t == 0) {
        orow[0] = 0.0f;
        orow[TSTEPS + 1] = (n == TSTEPS) ? 1.0f : 0.0f;
    }
}

// ---------------------------------------------------------------------------
// Launch. Inputs: 0 context 1 weight_ih(unused) 2 weight_hh 3 bias_ih
//                 4 bias_hh 5 fc_w 6 fc_b 7 num_pred_list 8 max_steps
// ---------------------------------------------------------------------------
extern "C" void kernel_launch(void* const* d_in, const int* in_sizes, int n_in,
                              void* d_out, int out_size)
{
    const float* context  = (const float*)d_in[0];
    const float* Whh      = (const float*)d_in[2];
    const float* bias_ih  = (const float*)d_in[3];
    const float* bias_hh  = (const float*)d_in[4];
    const float* fc_w     = (const float*)d_in[5];
    const float* fc_b     = (const float*)d_in[6];
    const int*   num_pred = (const int*)d_in[7];
    float*       out      = (float*)d_out;

    static bool attr_set = false;
    if (!attr_set) {
        cudaFuncSetAttribute(persist_kernel,
                             cudaFuncAttributeMaxDynamicSharedMemorySize, SMEM_DYN);
        attr_set = true;
    }

    prep_w_kernel<<<(H3 * HDIM + 255) / 256, 256>>>(Whh);
    prep_h_kernel<<<(BSZ * HDIM + 255) / 256, 256>>>(context);

    dim3 grid(NJB, BSZ / MTILE);  // (32, 4) = 128 CTAs, 1 per SM
    persist_kernel<<<grid, NTHREADS, SMEM_DYN>>>(context, bias_ih, bias_hh, fc_w);

    finalize_kernel<<<BSZ, TSTEPS>>>(num_pred, fc_b, out);
}

// round 11
// speedup vs baseline: 2.7833x; 1.3041x over previous
#include <cuda_runtime.h>
#include <cuda_bf16.h>
#include <math.h>
#include <stdint.h>

// Problem constants
#define BSZ    256
#define HDIM   768
#define H3     2304
#define TSTEPS 128

// Tiling
#define JT       24               // j-columns per CTA (per gate)
#define NB       72               // 3 gates * JT rows of W per CTA
#define MTILE    64               // batch rows per CTA
#define NKC      12               // 64-wide k-chunks
#define NPAIR    6                // pipeline iterations (2 k-chunks each)
#define NSTAGE   3                // A ring depth
#define NTHREADS 384              // 12 warps
#define NJB      (HDIM / JT)      // 32
#define NGRP     32               // CTAs per barrier group (one batch-tile row)

// Dynamic SMEM layout (bytes)
//   W resident (single bf16): [chunk(12)][row(72)][128B], SW128 = 110592
//   A ring (single bf16 h): [stage(3)][sub(2)][row(64)][128B]
#define WCH      (NB * 128)                    // 9216 per chunk
#define WBYTES   (NKC * WCH)                   // 110592
#define AOFF     WBYTES
#define ASUB     (MTILE * 128)                 // 8192
#define ABUF     (2 * ASUB)                    // 16384 per stage (2 sub-chunks)
#define SMEM_DYN (AOFF + NSTAGE * ABUF)        // 159744
#define CSTRIDE  73                            // fp32 C row stride in epilogue

// ---------------------------------------------------------------------------
// Device globals
// ---------------------------------------------------------------------------
__device__ __align__(16) __nv_bfloat16 g_hb[2][BSZ * HDIM];  // bf16 h
__device__ __align__(16) __nv_bfloat16 g_wh[H3 * HDIM];      // single bf16 W
__device__ float    g_dotp[TSTEPS * NJB * BSZ];
__device__ unsigned g_barg[4 * 32];   // 4 group counters, 128B apart

// ---------------------------------------------------------------------------
// PTX helpers (baseline sm_80/90 features only — NO tcgen05)
// ---------------------------------------------------------------------------
__device__ __forceinline__ uint32_t smem_u32(const void* p) {
    uint32_t a;
    asm("{ .reg .u64 t; cvta.to.shared.u64 t, %1; cvt.u32.u64 %0, t; }"
        : "=r"(a) : "l"(p));
    return a;
}
__device__ __forceinline__ void cp16(uint32_t d, const void* s) {
    asm volatile("cp.async.cg.shared.global [%0], [%1], 16;" :: "r"(d), "l"(s));
}
__device__ __forceinline__ void cp_commit() {
    asm volatile("cp.async.commit_group;" ::: "memory");
}
template <int N>
__device__ __forceinline__ void cp_wait() {
    asm volatile("cp.async.wait_group %0;" :: "n"(N) : "memory");
}
__device__ __forceinline__ void ldsm_x4(uint32_t* r, uint32_t a) {
    asm volatile("ldmatrix.sync.aligned.m8n8.x4.shared.b16 {%0,%1,%2,%3}, [%4];"
                 : "=r"(r[0]), "=r"(r[1]), "=r"(r[2]), "=r"(r[3]) : "r"(a));
}
__device__ __forceinline__ void ldsm_x2(uint32_t* r, uint32_t a) {
    asm volatile("ldmatrix.sync.aligned.m8n8.x2.shared.b16 {%0,%1}, [%2];"
                 : "=r"(r[0]), "=r"(r[1]) : "r"(a));
}
__device__ __forceinline__ void mma_bf16(float* c, const uint32_t* a, const uint32_t* b) {
    asm volatile(
        "mma.sync.aligned.m16n8k16.row.col.f32.bf16.bf16.f32 "
        "{%0,%1,%2,%3}, {%4,%5,%6,%7}, {%8,%9}, {%0,%1,%2,%3};"
        : "+f"(c[0]), "+f"(c[1]), "+f"(c[2]), "+f"(c[3])
        : "r"(a[0]), "r"(a[1]), "r"(a[2]), "r"(a[3]), "r"(b[0]), "r"(b[1]));
}
#define SW128(o) ((o) ^ (((o) >> 3) & 0x70))

// ---------------------------------------------------------------------------
// Prep kernels
// ---------------------------------------------------------------------------
__global__ void prep_w_kernel(const float* __restrict__ W) {
    int i = blockIdx.x * blockDim.x + threadIdx.x;
    if (i < H3 * HDIM) g_wh[i] = __float2bfloat16_rn(W[i]);
}
__global__ void prep_h_kernel(const float* __restrict__ ctx) {
    int i = blockIdx.x * blockDim.x + threadIdx.x;
    if (i < 4 * 32) g_barg[i] = 0u;
    if (i < BSZ * HDIM) g_hb[0][i] = __float2bfloat16_rn(ctx[i]);
}

// ---------------------------------------------------------------------------
// Group barrier: 32 CTAs sharing one batch-tile row (all co-resident)
// ---------------------------------------------------------------------------
__device__ __forceinline__ void group_barrier(unsigned* ctr, unsigned target) {
    __syncthreads();
    if (threadIdx.x == 0) {
        __threadfence();
        atomicAdd(ctr, 1u);
        unsigned v;
        do { v = *(volatile unsigned*)ctr; } while (v < target);
        __threadfence();
    }
    __syncthreads();
}

// ---------------------------------------------------------------------------
// Persistent kernel: all 128 GRU steps.
// Grid (32, 4), 384 threads = 12 warps, warp tile 16x24 over CTA tile 64x72.
// Single-term bf16: C = bf16(h) @ bf16(W). 3-stage A ring, 1 sync per stage.
// ---------------------------------------------------------------------------
__global__ __launch_bounds__(NTHREADS, 1) void persist_kernel(
    const float* __restrict__ context,
    const float* __restrict__ bias_ih,
    const float* __restrict__ bias_hh,
    const float* __restrict__ fc_w)
{
    extern __shared__ __align__(16) uint8_t smem[];
    __shared__ float sbr[JT], sbz[JT], sbni[JT], sbnh[JT], sfw[JT];

    const uint32_t sbase = smem_u32(smem);
    const int tid    = threadIdx.x;
    const int lane   = tid & 31;
    const int wid    = tid >> 5;
    const int warp_m = (wid & 3) * 16;     // 4 m-tiles of 16 (M=64)
    const int warp_n = (wid >> 2) * 24;    // 3 n-tiles of 24 (N=72)
    const int jb     = blockIdx.x;
    const int j0     = jb * JT;
    const int brow   = blockIdx.y * MTILE;
    unsigned* bctr   = &g_barg[blockIdx.y * 32];

    // Epilogue ownership: threads 0..255 = (batch row, j-group of 6)
    const int eb  = tid >> 2;              // 0..63 (for tid<256)
    const int ejq = (tid & 3) * 6;         // 0,6,12,18

    // ---- stage resident W (single bf16) into SMEM, SW128 swizzled ----
    for (int idx = tid; idx < NKC * NB * 8; idx += NTHREADS) {
        int ck  = idx / (NB * 8);
        int rem = idx - ck * (NB * 8);
        int r   = rem >> 3, cg = rem & 7;
        int wrow = (r / JT) * HDIM + j0 + (r % JT);
        size_t so = (size_t)wrow * HDIM + ck * 64 + cg * 8;
        uint32_t dst = (uint32_t)(ck * WCH) + SW128((uint32_t)(r * 128 + cg * 16));
        cp16(sbase + dst, g_wh + so);
    }
    cp_commit();   // W group

    if (tid < JT) {
        int j = j0 + tid;
        sbr[tid]  = bias_ih[j] + bias_hh[j];
        sbz[tid]  = bias_ih[HDIM + j] + bias_hh[HDIM + j];
        sbni[tid] = bias_ih[2 * HDIM + j];
        sbnh[tid] = bias_hh[2 * HDIM + j];
        sfw[tid]  = fc_w[j];
    }

    // fp32 h in registers: thread (tid<256) owns (brow+eb, j0+ejq..+5)
    float hreg[6];
    if (tid < 256) {
        const float* crow = context + (size_t)(brow + eb) * HDIM + j0 + ejq;
#pragma unroll
        for (int jj = 0; jj < 6; jj++) hreg[jj] = crow[jj];
    }
    __syncthreads();

    unsigned bar_target = 0;
    for (int t = 0; t < TSTEPS; t++) {
        const int rp = t & 1;
        const int wp = rp ^ 1;
        const __nv_bfloat16* __restrict__ hb = g_hb[rp];

        float acc[3][4];
#pragma unroll
        for (int ni = 0; ni < 3; ni++)
#pragma unroll
            for (int q = 0; q < 4; q++) acc[ni][q] = 0.0f;

        // pair-stage p covers k-chunks 2p, 2p+1 (128 K elems); stage = p % 3
        auto issueA = [&](int p) {
            const uint32_t abase = sbase + AOFF + (uint32_t)(p % NSTAGE) * ABUF;
            const int k0 = p * 128;
            for (int idx = tid; idx < MTILE * 16; idx += NTHREADS) {  // ~2.7 iters
                int r = idx >> 4, cg = idx & 15;
                int sub = cg >> 3, cgi = cg & 7;
                uint32_t off = (uint32_t)(sub * ASUB) +
                               SW128((uint32_t)(r * 128 + cgi * 16));
                size_t so = (size_t)(brow + r) * HDIM + k0 + sub * 64 + cgi * 8;
                cp16(abase + off, hb + so);
            }
            cp_commit();
        };

        auto compute = [&](int p) {
            const uint32_t abase = sbase + AOFF + (uint32_t)(p % NSTAGE) * ABUF;
#pragma unroll
            for (int sub = 0; sub < 2; sub++) {
                const uint32_t asb   = abase + sub * ASUB;
                const uint32_t wbase = sbase + (uint32_t)((2 * p + sub) * WCH);
#pragma unroll
                for (int ks = 0; ks < 4; ks++) {
                    const uint32_t kb = ks * 32;
                    uint32_t ah[4], bw[3][2];
                    {
                        uint32_t off = SW128(
                            (uint32_t)((warp_m + (lane & 15)) * 128) + kb +
                            ((lane >> 4) & 1) * 16);
                        ldsm_x4(ah, asb + off);
                    }
#pragma unroll
                    for (int ni = 0; ni < 3; ni++) {
                        uint32_t off = SW128(
                            (uint32_t)((warp_n + ni * 8 + (lane & 7)) * 128) + kb +
                            ((lane >> 3) & 1) * 16);
                        ldsm_x2(bw[ni], wbase + off);
                    }
#pragma unroll
                    for (int ni = 0; ni < 3; ni++)
                        mma_bf16(acc[ni], ah, bw[ni]);
                }
            }
        };

        // ---- 3-stage pipelined loop: 1 sync per pair-stage ----
        issueA(0);
        issueA(1);
        for (int p = 0; p < NPAIR; p++) {
            if (p == NPAIR - 1) cp_wait<0>();
            else                cp_wait<1>();
            __syncthreads();
            if (p + 2 < NPAIR) issueA(p + 2);
            compute(p);
        }

        // ---- C to SMEM (spans stage 0 + head of stage 1; last reads of s0/s1
        //      were compute(3)/compute(4), sequenced before the p=5 sync;
        //      compute(5) reads only s2 — no overlap) ----
        float* Csm = (float*)(smem + AOFF);
        {
            const int r0 = lane >> 2, cpn = (lane & 3) * 2;
#pragma unroll
            for (int ni = 0; ni < 3; ni++) {
                int row = warp_m + r0;
                int col = warp_n + ni * 8 + cpn;
                Csm[row * CSTRIDE + col]           = acc[ni][0];
                Csm[row * CSTRIDE + col + 1]       = acc[ni][1];
                Csm[(row + 8) * CSTRIDE + col]     = acc[ni][2];
                Csm[(row + 8) * CSTRIDE + col + 1] = acc[ni][3];
            }
        }
        __syncthreads();

        // ---- gate epilogue: threads 0..255 = (row, j-group of 6) ----
        if (tid < 256) {
            const int b = brow + eb;
            __nv_bfloat16* __restrict__ hbo = g_hb[wp] + (size_t)b * HDIM + j0 + ejq;
            const float* crow = Csm + eb * CSTRIDE;

            float part = 0.0f;
#pragma unroll
            for (int q = 0; q < 6; q++) {
                const int jj = ejq + q;
                float rawr = crow[jj];
                float rawz = crow[JT + jj];
                float rawn = crow[2 * JT + jj];

                float rg = 1.0f / (1.0f + expf(-(sbr[jj] + rawr)));
                float zg = 1.0f / (1.0f + expf(-(sbz[jj] + rawz)));
                float ng = tanhf(sbni[jj] + rg * (rawn + sbnh[jj]));
                float hn = (1.0f - zg) * ng + zg * hreg[q];

                hreg[q] = hn;
                hbo[q] = __float2bfloat16_rn(hn);
                part += hn * sfw[jj];
            }
            part += __shfl_xor_sync(0xFFFFFFFFu, part, 1);
            part += __shfl_xor_sync(0xFFFFFFFFu, part, 2);
            if ((tid & 3) == 0)
                g_dotp[(size_t)t * NJB * BSZ + jb * BSZ + b] = part;
        }

        // group barrier (leading __syncthreads also protects Csm reuse)
        bar_target += NGRP;
        if (t + 1 < TSTEPS) group_barrier(bctr, bar_target);
    }
}

// ---------------------------------------------------------------------------
// Finalize: dot = fixed-order sum of 32 partials, softplus, scan, normalize
// ---------------------------------------------------------------------------
__device__ __forceinline__ float softplusf_(float x) {
    return (x > 0.0f) ? (x + log1pf(expf(-x))) : log1pf(expf(x));
}

__global__ __launch_bounds__(TSTEPS) void finalize_kernel(
    const int* __restrict__ num_pred,
    const float* __restrict__ fc_b,
    float* __restrict__ out)
{
    __shared__ float s[TSTEPS];
    const int b = blockIdx.x;
    const int t = threadIdx.x;

    float dot = fc_b[0];
    const float* p = g_dotp + (size_t)t * NJB * BSZ + b;
#pragma unroll
    for (int jbk = 0; jbk < NJB; jbk++) dot += p[jbk * BSZ];
    s[t] = softplusf_(dot);
    __syncthreads();

#pragma unroll
    for (int off = 1; off < TSTEPS; off <<= 1) {
        float v = (t >= off) ? s[t - off] : 0.0f;
        __syncthreads();
        s[t] += v;
        __syncthreads();
    }

    const int n = num_pred[b];
    int idx = n - 1;
    if (idx < 0) idx = 0;
    if (idx > TSTEPS - 1) idx = TSTEPS - 1;
    const float last = s[idx] + 1e-6f;

    float* orow = out + (size_t)b * (TSTEPS + 2);
    float val;
    if (t < n)       val = s[t] / last;
    else if (t == n) val = 1.0f;
    else             val = 0.0f;
    orow[t + 1] = val;

    if (t == 0) {
        orow[0] = 0.0f;
        orow[TSTEPS + 1] = (n == TSTEPS) ? 1.0f : 0.0f;
    }
}

// ---------------------------------------------------------------------------
// Launch. Inputs: 0 context 1 weight_ih(unused) 2 weight_hh 3 bias_ih
//                 4 bias_hh 5 fc_w 6 fc_b 7 num_pred_list 8 max_steps
// ---------------------------------------------------------------------------
extern "C" void kernel_launch(void* const* d_in, const int* in_sizes, int n_in,
                              void* d_out, int out_size)
{
    const float* context  = (const float*)d_in[0];
    const float* Whh      = (const float*)d_in[2];
    const float* bias_ih  = (const float*)d_in[3];
    const float* bias_hh  = (const float*)d_in[4];
    const float* fc_w     = (const float*)d_in[5];
    const float* fc_b     = (const float*)d_in[6];
    const int*   num_pred = (const int*)d_in[7];
    float*       out      = (float*)d_out;

    static bool attr_set = false;
    if (!attr_set) {
        cudaFuncSetAttribute(persist_kernel,
                             cudaFuncAttributeMaxDynamicSharedMemorySize, SMEM_DYN);
        attr_set = true;
    }

    prep_w_kernel<<<(H3 * HDIM + 255) / 256, 256>>>(Whh);
    prep_h_kernel<<<(BSZ * HDIM + 255) / 256, 256>>>(context);

    dim3 grid(NJB, BSZ / MTILE);  // (32, 4) = 128 CTAs, 1 per SM
    persist_kernel<<<grid, NTHREADS, SMEM_DYN>>>(context, bias_ih, bias_hh, fc_w);

    finalize_kernel<<<BSZ, TSTEPS>>>(num_pred, fc_b, out);
}

// round 12
// speedup vs baseline: 2.9411x; 1.0567x over previous
#include <cuda_runtime.h>
#include <cuda_bf16.h>
#include <math.h>
#include <stdint.h>

// Problem constants
#define BSZ    256
#define HDIM   768
#define H3     2304
#define TSTEPS 128

// Tiling
#define JT       24               // j-columns per CTA (per gate)
#define NB       72               // 3 gates * JT rows of W per CTA
#define MTILE    64               // batch rows per CTA
#define NKC      12               // 64-wide k-chunks
#define NTHREADS 384              // 12 warps
#define NJB      (HDIM / JT)      // 32
#define NGRP     32               // CTAs per barrier group (one batch-tile row)

// Dynamic SMEM layout (bytes)
//   W resident (bf16): [chunk(12)][row(72)][128B], SW128 = 110592
//   A resident (bf16 h): [chunk(12)][row(64)][128B], SW128 = 98304
#define WCH      (NB * 128)                    // 9216 per W chunk
#define WBYTES   (NKC * WCH)                   // 110592
#define AOFF     WBYTES
#define ACH      (MTILE * 128)                 // 8192 per A chunk
#define SMEM_DYN (AOFF + NKC * ACH)            // 208896
#define CSTRIDE  73                            // fp32 C row stride in epilogue

// ---------------------------------------------------------------------------
// Device globals
// ---------------------------------------------------------------------------
__device__ __align__(16) __nv_bfloat16 g_hb[2][BSZ * HDIM];  // bf16 h
__device__ __align__(16) __nv_bfloat16 g_wh[H3 * HDIM];      // bf16 W
__device__ float    g_dotp[TSTEPS * NJB * BSZ];
__device__ unsigned g_barg[4 * 32];   // 4 group counters, 128B apart

// ---------------------------------------------------------------------------
// PTX helpers (baseline sm_80/90 features only — NO tcgen05)
// ---------------------------------------------------------------------------
__device__ __forceinline__ uint32_t smem_u32(const void* p) {
    uint32_t a;
    asm("{ .reg .u64 t; cvta.to.shared.u64 t, %1; cvt.u32.u64 %0, t; }"
        : "=r"(a) : "l"(p));
    return a;
}
__device__ __forceinline__ void cp16(uint32_t d, const void* s) {
    asm volatile("cp.async.cg.shared.global [%0], [%1], 16;" :: "r"(d), "l"(s));
}
__device__ __forceinline__ void cp_commit() {
    asm volatile("cp.async.commit_group;" ::: "memory");
}
template <int N>
__device__ __forceinline__ void cp_wait() {
    asm volatile("cp.async.wait_group %0;" :: "n"(N) : "memory");
}
__device__ __forceinline__ void ldsm_x4(uint32_t* r, uint32_t a) {
    asm volatile("ldmatrix.sync.aligned.m8n8.x4.shared.b16 {%0,%1,%2,%3}, [%4];"
                 : "=r"(r[0]), "=r"(r[1]), "=r"(r[2]), "=r"(r[3]) : "r"(a));
}
__device__ __forceinline__ void ldsm_x2(uint32_t* r, uint32_t a) {
    asm volatile("ldmatrix.sync.aligned.m8n8.x2.shared.b16 {%0,%1}, [%2];"
                 : "=r"(r[0]), "=r"(r[1]) : "r"(a));
}
__device__ __forceinline__ void mma_bf16(float* c, const uint32_t* a, const uint32_t* b) {
    asm volatile(
        "mma.sync.aligned.m16n8k16.row.col.f32.bf16.bf16.f32 "
        "{%0,%1,%2,%3}, {%4,%5,%6,%7}, {%8,%9}, {%0,%1,%2,%3};"
        : "+f"(c[0]), "+f"(c[1]), "+f"(c[2]), "+f"(c[3])
        : "r"(a[0]), "r"(a[1]), "r"(a[2]), "r"(a[3]), "r"(b[0]), "r"(b[1]));
}
#define SW128(o) ((o) ^ (((o) >> 3) & 0x70))

// ---------------------------------------------------------------------------
// Prep kernels
// ---------------------------------------------------------------------------
__global__ void prep_w_kernel(const float* __restrict__ W) {
    int i = blockIdx.x * blockDim.x + threadIdx.x;
    if (i < H3 * HDIM) g_wh[i] = __float2bfloat16_rn(W[i]);
}
__global__ void prep_h_kernel(const float* __restrict__ ctx) {
    int i = blockIdx.x * blockDim.x + threadIdx.x;
    if (i < 4 * 32) g_barg[i] = 0u;
    if (i < BSZ * HDIM) g_hb[0][i] = __float2bfloat16_rn(ctx[i]);
}

// ---------------------------------------------------------------------------
// Group barrier: 32 CTAs sharing one batch-tile row (all co-resident)
// ---------------------------------------------------------------------------
__device__ __forceinline__ void group_barrier(unsigned* ctr, unsigned target) {
    __syncthreads();
    if (threadIdx.x == 0) {
        __threadfence();
        atomicAdd(ctr, 1u);
        unsigned v;
        do { v = *(volatile unsigned*)ctr; } while (v < target);
        __threadfence();
    }
    __syncthreads();
}

// ---------------------------------------------------------------------------
// Persistent kernel: all 128 GRU steps.
// Grid (32, 4), 384 threads = 12 warps, warp tile 16x24 over CTA tile 64x72.
// Single-term bf16. A fully SMEM-resident per step; 2 waits + 2 syncs/step.
// ---------------------------------------------------------------------------
__global__ __launch_bounds__(NTHREADS, 1) void persist_kernel(
    const float* __restrict__ context,
    const float* __restrict__ bias_ih,
    const float* __restrict__ bias_hh,
    const float* __restrict__ fc_w)
{
    extern __shared__ __align__(16) uint8_t smem[];
    __shared__ float sbr[JT], sbz[JT], sbni[JT], sbnh[JT], sfw[JT];

    const uint32_t sbase = smem_u32(smem);
    const int tid    = threadIdx.x;
    const int lane   = tid & 31;
    const int wid    = tid >> 5;
    const int warp_m = (wid & 3) * 16;     // 4 m-tiles of 16 (M=64)
    const int warp_n = (wid >> 2) * 24;    // 3 n-tiles of 24 (N=72)
    const int jb     = blockIdx.x;
    const int j0     = jb * JT;
    const int brow   = blockIdx.y * MTILE;
    unsigned* bctr   = &g_barg[blockIdx.y * 32];

    // Epilogue ownership: threads 0..255 = (batch row, j-group of 6)
    const int eb  = tid >> 2;              // 0..63 (for tid<256)
    const int ejq = (tid & 3) * 6;         // 0,6,12,18

    // ---- stage resident W (bf16) into SMEM, SW128 swizzled ----
    for (int idx = tid; idx < NKC * NB * 8; idx += NTHREADS) {
        int ck  = idx / (NB * 8);
        int rem = idx - ck * (NB * 8);
        int r   = rem >> 3, cg = rem & 7;
        int wrow = (r / JT) * HDIM + j0 + (r % JT);
        size_t so = (size_t)wrow * HDIM + ck * 64 + cg * 8;
        uint32_t dst = (uint32_t)(ck * WCH) + SW128((uint32_t)(r * 128 + cg * 16));
        cp16(sbase + dst, g_wh + so);
    }
    cp_commit();   // W group

    if (tid < JT) {
        int j = j0 + tid;
        sbr[tid]  = bias_ih[j] + bias_hh[j];
        sbz[tid]  = bias_ih[HDIM + j] + bias_hh[HDIM + j];
        sbni[tid] = bias_ih[2 * HDIM + j];
        sbnh[tid] = bias_hh[2 * HDIM + j];
        sfw[tid]  = fc_w[j];
    }

    // fp32 h in registers: thread (tid<256) owns (brow+eb, j0+ejq..+5)
    float hreg[6];
    if (tid < 256) {
        const float* crow = context + (size_t)(brow + eb) * HDIM + j0 + ejq;
#pragma unroll
        for (int jj = 0; jj < 6; jj++) hreg[jj] = crow[jj];
    }
    __syncthreads();

    unsigned bar_target = 0;
    for (int t = 0; t < TSTEPS; t++) {
        const int rp = t & 1;
        const int wp = rp ^ 1;
        const __nv_bfloat16* __restrict__ hb = g_hb[rp];

        float acc[3][4];
#pragma unroll
        for (int ni = 0; ni < 3; ni++)
#pragma unroll
            for (int q = 0; q < 4; q++) acc[ni][q] = 0.0f;

        // issue half (6 chunks = 3072 cp16, 8 per thread), one commit group
        auto issueHalf = [&](int half) {
            const int c0 = half * 6;
#pragma unroll
            for (int i = 0; i < 8; i++) {
                int idx = tid + i * NTHREADS;          // 0..3071
                int ck  = c0 + (idx >> 9);             // /512
                int rem = idx & 511;
                int r = rem >> 3, cg = rem & 7;
                uint32_t dst = (uint32_t)(AOFF + ck * ACH) +
                               SW128((uint32_t)(r * 128 + cg * 16));
                size_t so = (size_t)(brow + r) * HDIM + ck * 64 + cg * 8;
                cp16(sbase + dst, hb + so);
            }
            cp_commit();
        };

        auto compute = [&](int ck) {
            const uint32_t asb   = sbase + AOFF + (uint32_t)(ck * ACH);
            const uint32_t wbase = sbase + (uint32_t)(ck * WCH);
#pragma unroll
            for (int ks = 0; ks < 4; ks++) {
                const uint32_t kb = ks * 32;
                uint32_t ah[4], bw[3][2];
                {
                    uint32_t off = SW128(
                        (uint32_t)((warp_m + (lane & 15)) * 128) + kb +
                        ((lane >> 4) & 1) * 16);
                    ldsm_x4(ah, asb + off);
                }
#pragma unroll
                for (int ni = 0; ni < 3; ni++) {
                    uint32_t off = SW128(
                        (uint32_t)((warp_n + ni * 8 + (lane & 7)) * 128) + kb +
                        ((lane >> 3) & 1) * 16);
                    ldsm_x2(bw[ni], wbase + off);
                }
#pragma unroll
                for (int ni = 0; ni < 3; ni++)
                    mma_bf16(acc[ni], ah, bw[ni]);
            }
        };

        // ---- 2-phase step: all A resident, 2 waits + 2 syncs ----
        issueHalf(0);
        issueHalf(1);
        cp_wait<1>();          // half 0 (and W, step 0) complete
        __syncthreads();
#pragma unroll
        for (int ck = 0; ck < 6; ck++) compute(ck);
        cp_wait<0>();          // half 1 complete
        __syncthreads();       // also: all first-half computes done (A chunks 0-2 free)
#pragma unroll
        for (int ck = 6; ck < 12; ck++) compute(ck);

        // ---- C to SMEM (overlays A chunks 0-2; safe per mid-sync argument) ----
        float* Csm = (float*)(smem + AOFF);
        {
            const int r0 = lane >> 2, cpn = (lane & 3) * 2;
#pragma unroll
            for (int ni = 0; ni < 3; ni++) {
                int row = warp_m + r0;
                int col = warp_n + ni * 8 + cpn;
                Csm[row * CSTRIDE + col]           = acc[ni][0];
                Csm[row * CSTRIDE + col + 1]       = acc[ni][1];
                Csm[(row + 8) * CSTRIDE + col]     = acc[ni][2];
                Csm[(row + 8) * CSTRIDE + col + 1] = acc[ni][3];
            }
        }
        __syncthreads();

        // ---- gate epilogue: threads 0..255 = (row, j-group of 6) ----
        if (tid < 256) {
            const int b = brow + eb;
            __nv_bfloat16* __restrict__ hbo = g_hb[wp] + (size_t)b * HDIM + j0 + ejq;
            const float* crow = Csm + eb * CSTRIDE;

            float part = 0.0f;
#pragma unroll
            for (int q = 0; q < 6; q++) {
                const int jj = ejq + q;
                float rawr = crow[jj];
                float rawz = crow[JT + jj];
                float rawn = crow[2 * JT + jj];

                float rg = 1.0f / (1.0f + expf(-(sbr[jj] + rawr)));
                float zg = 1.0f / (1.0f + expf(-(sbz[jj] + rawz)));
                float ng = tanhf(sbni[jj] + rg * (rawn + sbnh[jj]));
                float hn = (1.0f - zg) * ng + zg * hreg[q];

                hreg[q] = hn;
                hbo[q] = __float2bfloat16_rn(hn);
                part += hn * sfw[jj];
            }
            part += __shfl_xor_sync(0xFFFFFFFFu, part, 1);
            part += __shfl_xor_sync(0xFFFFFFFFu, part, 2);
            if ((tid & 3) == 0)
                g_dotp[(size_t)t * NJB * BSZ + jb * BSZ + b] = part;
        }

        // group barrier (leading __syncthreads also protects Csm/A reuse)
        bar_target += NGRP;
        if (t + 1 < TSTEPS) group_barrier(bctr, bar_target);
    }
}

// ---------------------------------------------------------------------------
// Finalize: dot = fixed-order sum of 32 partials, softplus, scan, normalize
// ---------------------------------------------------------------------------
__device__ __forceinline__ float softplusf_(float x) {
    return (x > 0.0f) ? (x + log1pf(expf(-x))) : log1pf(expf(x));
}

__global__ __launch_bounds__(TSTEPS) void finalize_kernel(
    const int* __restrict__ num_pred,
    const float* __restrict__ fc_b,
    float* __restrict__ out)
{
    __shared__ float s[TSTEPS];
    const int b = blockIdx.x;
    const int t = threadIdx.x;

    float dot = fc_b[0];
    const float* p = g_dotp + (size_t)t * NJB * BSZ + b;
#pragma unroll
    for (int jbk = 0; jbk < NJB; jbk++) dot += p[jbk * BSZ];
    s[t] = softplusf_(dot);
    __syncthreads();

#pragma unroll
    for (int off = 1; off < TSTEPS; off <<= 1) {
        float v = (t >= off) ? s[t - off] : 0.0f;
        __syncthreads();
        s[t] += v;
        __syncthreads();
    }

    const int n = num_pred[b];
    int idx = n - 1;
    if (idx < 0) idx = 0;
    if (idx > TSTEPS - 1) idx = TSTEPS - 1;
    const float last = s[idx] + 1e-6f;

    float* orow = out + (size_t)b * (TSTEPS + 2);
    float val;
    if (t < n)       val = s[t] / last;
    else if (t == n) val = 1.0f;
    else             val = 0.0f;
    orow[t + 1] = val;

    if (t == 0) {
        orow[0] = 0.0f;
        orow[TSTEPS + 1] = (n == TSTEPS) ? 1.0f : 0.0f;
    }
}

// ---------------------------------------------------------------------------
// Launch. Inputs: 0 context 1 weight_ih(unused) 2 weight_hh 3 bias_ih
//                 4 bias_hh 5 fc_w 6 fc_b 7 num_pred_list 8 max_steps
// ---------------------------------------------------------------------------
extern "C" void kernel_launch(void* const* d_in, const int* in_sizes, int n_in,
                              void* d_out, int out_size)
{
    const float* context  = (const float*)d_in[0];
    const float* Whh      = (const float*)d_in[2];
    const float* bias_ih  = (const float*)d_in[3];
    const float* bias_hh  = (const float*)d_in[4];
    const float* fc_w     = (const float*)d_in[5];
    const float* fc_b     = (const float*)d_in[6];
    const int*   num_pred = (const int*)d_in[7];
    float*       out      = (float*)d_out;

    static bool attr_set = false;
    if (!attr_set) {
        cudaFuncSetAttribute(persist_kernel,
                             cudaFuncAttributeMaxDynamicSharedMemorySize, SMEM_DYN);
        attr_set = true;
    }

    prep_w_kernel<<<(H3 * HDIM + 255) / 256, 256>>>(Whh);
    prep_h_kernel<<<(BSZ * HDIM + 255) / 256, 256>>>(context);

    dim3 grid(NJB, BSZ / MTILE);  // (32, 4) = 128 CTAs, 1 per SM
    persist_kernel<<<grid, NTHREADS, SMEM_DYN>>>(context, bias_ih, bias_hh, fc_w);

    finalize_kernel<<<BSZ, TSTEPS>>>(num_pred, fc_b, out);
}